// round 7
// baseline (speedup 1.0000x reference)
#include <cuda_runtime.h>
#include <cstddef>

// PathSampling:
//  paths      [n_node, 32, 8] int32
//  edge_ids   [n_node, 32, 7] int32
//  rand_lens  [n_node, 32]    int32
//  centrality [n_graph]       float32
//  k_path = 8
//
// masked_paths[n,p,j] = (j > rand_lens[n,p]) ? -1 : paths[n,p,j]
// score[n,p] = sum_j centrality[masked_paths[n,p,j]] (masked -> +0, exact)
// top-8 paths per node by score (ties: lower path index, per lax.top_k)
// out (float32): concat(paths_sel [n,8,8], edge_ids_sel [n,8,7]); values
// int->float (exact: ids < 2^24; mask -> -1.0f).
//
// Selection via warp bitonic sort on key = (score_bits << 5) | (31 - lane):
// scores are sums of non-negative floats, so uint bit order == value order;
// descending key order == (score desc, lane asc) == lax.top_k tie-break.
// Keys are distinct -> a permutation -> every output written exactly once.

#define N_PATH 32
#define L_PATH 8
#define K_SEL  8
#define E_PER  (L_PATH - 1)           // 7
#define E_TOT  (K_SEL * E_PER)        // 56

__global__ void __launch_bounds__(256, 8) path_sampling_kernel(
    const int*   __restrict__ paths,
    const int*   __restrict__ edge_ids,
    const int*   __restrict__ rand_lens,
    const float* __restrict__ centrality,
    float*       __restrict__ out_paths,   // [n_node, 8, 8] float32
    float*       __restrict__ out_edges,   // [n_node, 8, 7] float32 or nullptr
    int n_node)
{
    const int warp_id = (blockIdx.x * blockDim.x + threadIdx.x) >> 5;
    const int lane    = threadIdx.x & 31;
    if (warp_id >= n_node) return;
    const int node = warp_id;

    // rand_len for this lane's path (coalesced 128B per warp, read-once)
    const int rl = __ldcs(rand_lens + (size_t)node * N_PATH + lane);

    // This lane's 8 path node-ids: 2 x LDG.128.CS, coalesced, read-once
    const int4* p4 = reinterpret_cast<const int4*>(paths + (size_t)node * N_PATH * L_PATH);
    int4 a = __ldcs(p4 + lane * 2);
    int4 b = __ldcs(p4 + lane * 2 + 1);
    int pj[L_PATH] = {a.x, a.y, a.z, a.w, b.x, b.y, b.z, b.w};

    // Predicated centrality gathers (masked adds contribute exactly +0.0f,
    // identical to the reference's zero-padded gather). Loads up-front, MLP=8.
    float c[L_PATH];
#pragma unroll
    for (int j = 0; j < L_PATH; j++) {
        c[j] = (j <= rl) ? __ldg(centrality + pj[j]) : 0.0f;
    }
    float s = 0.0f;
#pragma unroll
    for (int j = 0; j < L_PATH; j++) s += c[j];   // sequential, matches jnp.sum

    // Mask the path values we will emit
#pragma unroll
    for (int j = 0; j < L_PATH; j++) {
        if (j > rl) pj[j] = -1;
    }

    // ---- warp bitonic sort, descending on 37-bit key ----
    // key order: larger score first; equal scores -> larger (31-lane) first
    // == smaller lane first (stable, matches lax.top_k).
    unsigned long long key =
        ((unsigned long long)__float_as_uint(s) << 5) |
        (unsigned long long)(31 - lane);
#pragma unroll
    for (int k = 2; k <= 32; k <<= 1) {
#pragma unroll
        for (int j = k >> 1; j > 0; j >>= 1) {
            unsigned long long other = __shfl_xor_sync(0xffffffffu, key, j);
            bool lower    = (lane & j) == 0;     // lower index of the pair
            bool asc      = (lane & k) == 0;     // region direction flag
            bool take_min = (lower != asc);      // reversed net => descending
            unsigned long long mn = key < other ? key : other;
            unsigned long long mx = key < other ? other : key;
            key = take_min ? mn : mx;
        }
    }
    // lane r now holds the r-th best path's key; source path/lane:
    const int srcl = 31 - (int)(key & 31ull);

    // Pull the winner's masked path row to lanes 0..7 (in-place shfl; all
    // lanes participate as sources).
#pragma unroll
    for (int j = 0; j < L_PATH; j++) {
        pj[j] = __shfl_sync(0xffffffffu, pj[j], srcl);
    }
    if (lane < K_SEL) {
        float4* op = reinterpret_cast<float4*>(out_paths + ((size_t)node * K_SEL + lane) * L_PATH);
        __stcs(op,     make_float4((float)pj[0], (float)pj[1], (float)pj[2], (float)pj[3]));
        __stcs(op + 1, make_float4((float)pj[4], (float)pj[5], (float)pj[6], (float)pj[7]));
    }

    // Cooperative edge copy: 32 lanes move the 56 selected edge ints.
    // Sources lie in one contiguous 896B block; destination is 224B contiguous.
    if (out_edges != nullptr) {
        const int* eb = edge_ids + (size_t)node * N_PATH * E_PER;
        float*     ew = out_edges + (size_t)node * E_TOT;

        {   // t = lane (0..31), w = t/7 in 0..4
            int t = lane;
            int w = t / E_PER;
            int j = t - w * E_PER;
            int sw = __shfl_sync(0xffffffffu, srcl, w);
            __stcs(ew + t, (float)__ldcs(eb + sw * E_PER + j));
        }
        {   // t = lane+32 (32..55), active lanes < 24
            int t = lane + 32;
            int w = t / E_PER;
            int j = t - w * E_PER;
            int sw = __shfl_sync(0xffffffffu, srcl, w & 7);
            if (t < E_TOT) {
                __stcs(ew + t, (float)__ldcs(eb + sw * E_PER + j));
            }
        }
    }
}

extern "C" void kernel_launch(void* const* d_in, const int* in_sizes, int n_in,
                              void* d_out, int out_size)
{
    // ---- bind inputs by size (immune to metadata ordering) ----
    const void* ptr[8];
    long long   sz[8];
    int m = n_in > 8 ? 8 : n_in;
    for (int i = 0; i < m; i++) { ptr[i] = d_in[i]; sz[i] = in_sizes[i]; }

    int i_paths = 0;
    for (int i = 1; i < m; i++) if (sz[i] > sz[i_paths]) i_paths = i;
    int i_edges = -1;
    for (int i = 0; i < m; i++) {
        if (i == i_paths) continue;
        if (i_edges < 0 || sz[i] > sz[i_edges]) i_edges = i;
    }

    const long long oo = (long long)out_size;
    const long long np_sz = sz[i_paths];
    long long n_node_ll;
    bool has_edges;
    if (oo % (K_SEL * (2 * L_PATH - 1)) == 0 && np_sz == (oo / 120) * 256) {
        n_node_ll = oo / 120;           // both outputs concatenated in d_out
        has_edges = true;
    } else if (oo % (K_SEL * L_PATH) == 0 && np_sz == (oo / 64) * 256) {
        n_node_ll = oo / 64;            // only paths_sel fits in d_out
        has_edges = false;
    } else {
        n_node_ll = np_sz / (N_PATH * L_PATH);
        has_edges = (oo >= n_node_ll * 120);
    }

    int i_lens = -1, i_cent = -1;
    for (int i = 0; i < m; i++) {
        if (i == i_paths || i == i_edges) continue;
        if (sz[i] == n_node_ll * N_PATH) i_lens = i;
    }
    for (int i = 0; i < m; i++) {
        if (i == i_paths || i == i_edges || i == i_lens) continue;
        if (sz[i] > 4) i_cent = i;
    }
    if (i_lens < 0) i_lens = 2;
    if (i_cent < 0) i_cent = 3;

    const int*   paths      = (const int*)  ptr[i_paths];
    const int*   edge_ids   = (const int*)  ptr[i_edges];
    const int*   rand_lens  = (const int*)  ptr[i_lens];
    const float* centrality = (const float*)ptr[i_cent];
    const int    n_node     = (int)n_node_ll;

    float* out_paths = (float*)d_out;
    float* out_edges = has_edges ? out_paths + (size_t)n_node * K_SEL * L_PATH
                                 : nullptr;

    const int threads = 256;                   // 8 warps/block, 1 node/warp
    const int blocks  = (n_node * 32 + threads - 1) / threads;
    path_sampling_kernel<<<blocks, threads>>>(paths, edge_ids, rand_lens,
                                              centrality, out_paths,
                                              out_edges, n_node);
}